// round 15
// baseline (speedup 1.0000x reference)
#include <cuda_runtime.h>

#define NS 4096
typedef unsigned long long u64;

// f32x2 packed math (sm_103a): one FFMA2 = 2 fp32 FMAs
#define PACKDUP(d, x)  asm("mov.b64 %0, {%1, %1};" : "=l"(d) : "f"(x))
#define FFMA2(d, a, b) asm("fma.rn.f32x2 %0, %1, %2, %0;" : "+l"(d) : "l"(a), "l"(b))
#define UNPACK64(lo, hi, v) asm("mov.b64 {%0, %1}, %2;" : "=f"(lo), "=f"(hi) : "l"(v))

// ---- scratch (device globals: no allocation allowed) ----
__device__ float g_P[512 * 256];     // prefix table  (c0,c1,c2)
__device__ float g_S[512 * 256];     // suffix table  (c5,c6,c7)
__device__ float g_V1[NS * 256];     // intermediate after level-3 GEMM
__device__ int   g_p[NS];
__device__ int   g_q[NS];
__device__ int   g_cnt3[8];          // zero-init at load; ticket re-zeros each run
__device__ int   g_cnt4[8];
__device__ int   g_b3[8 * NS];
__device__ int   g_b4[8 * NS];
__device__ int   g_done3;            // ticket counters for cleanup
__device__ int   g_done4;

#define GRID3 304                    // 272 gemm tiles (136 x 2 halves) + 32 suffix blocks
#define GRID4 272

// ---------------------------------------------------------------------------
// Setup: blocks 0-31 prefix-table GEMMs (c1 staged in smem), 32-47 decode
// with hierarchical (smem-first) bucketing.
__global__ void __launch_bounds__(256) k_setup(
    const float* __restrict__ c0, const float* __restrict__ c1,
    const float* __restrict__ c2, const int* __restrict__ coords,
    float* __restrict__ out)
{
    int bid = blockIdx.x;
    int tid = threadIdx.x;

    if (bid < 32) {
        // ---- prefix: P[(ab,c)][col] = T[ab] @ core2[:,c,col] ----
        __shared__ float sA[64 * 68];
        __shared__ float sB[64 * 68];
        __shared__ float sc0[64];
        int cdig = bid >> 2, col0 = (bid & 3) * 64;
        if (tid < 64) sc0[tid] = c0[tid];
        for (int e = tid; e < 4096; e += 256) sB[e] = c1[e];   // coalesced stage
        __syncthreads();
        // T[ab][r] from smem only
        for (int e = tid; e < 4096; e += 256) {
            int r = e >> 6, ab = e & 63;
            int a = ab >> 3, b = ab & 7;
            float acc = 0.f;
#pragma unroll
            for (int i = 0; i < 8; i++)
                acc += sc0[a * 8 + i] * sB[(i * 8 + b) * 64 + r];
            sA[r * 68 + ab] = acc;
        }
        __syncthreads();
        for (int e = tid; e < 4096; e += 256) {
            int r = e >> 6, cc = e & 63;
            sB[r * 68 + cc] = c2[(r * 8 + cdig) * 256 + col0 + cc];
        }
        __syncthreads();
        int ct = tid & 15, abt = tid >> 4;
        float acc[4][4] = {};
        for (int r = 0; r < 64; r++) {
            float4 tv = *(const float4*)&sA[r * 68 + abt * 4];
            float4 bv = *(const float4*)&sB[r * 68 + ct * 4];
            acc[0][0] += tv.x * bv.x; acc[0][1] += tv.x * bv.y; acc[0][2] += tv.x * bv.z; acc[0][3] += tv.x * bv.w;
            acc[1][0] += tv.y * bv.x; acc[1][1] += tv.y * bv.y; acc[1][2] += tv.y * bv.z; acc[1][3] += tv.y * bv.w;
            acc[2][0] += tv.z * bv.x; acc[2][1] += tv.z * bv.y; acc[2][2] += tv.z * bv.z; acc[2][3] += tv.z * bv.w;
            acc[3][0] += tv.w * bv.x; acc[3][1] += tv.w * bv.y; acc[3][2] += tv.w * bv.z; acc[3][3] += tv.w * bv.w;
        }
#pragma unroll
        for (int ii = 0; ii < 4; ii++) {
            int p = (abt * 4 + ii) * 8 + cdig;
            *(float4*)&g_P[p * 256 + col0 + ct * 4] =
                make_float4(acc[ii][0], acc[ii][1], acc[ii][2], acc[ii][3]);
        }
    } else {
        // ---- decode + zero out; smem histogram -> 8 global atomics/block ----
        __shared__ int h3[8], h4[8], base3[8], base4[8];
        int n = (bid - 32) * 256 + tid;
        if (tid < 8) { h3[tid] = 0; h4[tid] = 0; }
        __syncthreads();
        int d3 = 0, d4 = 0, l3 = 0, l4 = 0;
        bool valid = (n < NS);
        if (valid) {
            out[n] = 0.f;   // gemm4 halves accumulate via atomicAdd
            int x = coords[3 * n], y = coords[3 * n + 1], z = coords[3 * n + 2];
            int d[8];
#pragma unroll
            for (int l = 0; l < 8; l++) {
                int sh = 7 - l;
                d[l] = 4 * ((x >> sh) & 1) + 2 * ((y >> sh) & 1) + ((z >> sh) & 1);
            }
            g_p[n] = d[0] * 64 + d[1] * 8 + d[2];
            g_q[n] = d[5] * 64 + d[6] * 8 + d[7];
            d3 = d[3]; d4 = d[4];
            l3 = atomicAdd(&h3[d3], 1);
            l4 = atomicAdd(&h4[d4], 1);
        }
        __syncthreads();
        if (tid < 8)            base3[tid] = atomicAdd(&g_cnt3[tid], h3[tid]);
        else if (tid < 16)      base4[tid - 8] = atomicAdd(&g_cnt4[tid - 8], h4[tid - 8]);
        __syncthreads();
        if (valid) {
            g_b3[d3 * NS + base3[d3] + l3] = n;
            g_b4[d4 * NS + base4[d4] + l4] = n;
        }
    }
}

// ---------------------------------------------------------------------------
// Pipelined FFMA2 GEMM: 32 samples x 128 cols, K=256, 128 threads.
// colg = tid&31 (4 cols), sg = tid>>5 (8 samples = 4 packed pairs).
// Double-buffered Bs: one barrier per K-chunk.
// Shared = Ast[256][32] 32KB + Bs[2][32][128] 32KB = 64KB.

__device__ __forceinline__ int2 tile_map(const int* __restrict__ cnt, int t) {
    int acc = 0, c = -1, base = 0;
#pragma unroll
    for (int i = 0; i < 8; i++) {
        int tiles = (cnt[i] + 31) >> 5;
        if (c < 0 && t < acc + tiles) { c = i; base = (t - acc) * 32; }
        acc += tiles;
    }
    return make_int2(c, base);
}

#define TICKET_CLEAN(DONE, CNT, TOTAL)                                         \
    {                                                                          \
        __syncthreads();                                                       \
        if (tid == 0) {                                                        \
            int old = atomicAdd(&DONE, 1);                                     \
            if (old == (TOTAL) - 1) {                                          \
                _Pragma("unroll")                                              \
                for (int j = 0; j < 8; j++) CNT[j] = 0;                        \
                DONE = 0;                                                      \
            }                                                                  \
        }                                                                      \
    }

#define LDB(KC)                                                                \
    {                                                                          \
        _Pragma("unroll")                                                      \
        for (int p4 = 0; p4 < 8; p4++)                                         \
            nb[p4] = __ldg((const float4*)(Bg + ((KC) * 32 + p4 * 4 + brow) * 2048 + bcol)); \
    }
#define STB(BUF)                                                               \
    {                                                                          \
        _Pragma("unroll")                                                      \
        for (int p4 = 0; p4 < 8; p4++)                                         \
            *(float4*)&Bs[(BUF) * 4096 + (p4 * 4 + brow) * 128 + bcol] = nb[p4]; \
    }
#define CHUNK_COMPUTE(KC, BUF)                                                 \
    {                                                                          \
        _Pragma("unroll 8")                                                    \
        for (int kk = 0; kk < 32; kk++) {                                      \
            float4 b = *(const float4*)&Bs[(BUF) * 4096 + kk * 128 + colg * 4]; \
            u64 bd0, bd1, bd2, bd3;                                            \
            PACKDUP(bd0, b.x); PACKDUP(bd1, b.y);                              \
            PACKDUP(bd2, b.z); PACKDUP(bd3, b.w);                              \
            const u64* ap = (const u64*)&Ast[((KC) * 32 + kk) * 32 + sg * 8];  \
            u64 a0 = ap[0], a1 = ap[1], a2 = ap[2], a3 = ap[3];                \
            FFMA2(acc[0][0], a0, bd0); FFMA2(acc[0][1], a0, bd1);              \
            FFMA2(acc[0][2], a0, bd2); FFMA2(acc[0][3], a0, bd3);              \
            FFMA2(acc[1][0], a1, bd0); FFMA2(acc[1][1], a1, bd1);              \
            FFMA2(acc[1][2], a1, bd2); FFMA2(acc[1][3], a1, bd3);              \
            FFMA2(acc[2][0], a2, bd0); FFMA2(acc[2][1], a2, bd1);              \
            FFMA2(acc[2][2], a2, bd2); FFMA2(acc[2][3], a2, bd3);              \
            FFMA2(acc[3][0], a3, bd0); FFMA2(acc[3][1], a3, bd1);              \
            FFMA2(acc[3][2], a3, bd2); FFMA2(acc[3][3], a3, bd3);              \
        }                                                                      \
    }
#define GEMM_MAIN()                                                            \
    LDB(0); STB(0); __syncthreads();                                           \
    _Pragma("unroll 1")                                                        \
    for (int kc = 0; kc < 8; kc++) {                                           \
        if (kc < 7) LDB(kc + 1);                                               \
        CHUNK_COMPUTE(kc, kc & 1);                                             \
        if (kc < 7) { STB((kc + 1) & 1); __syncthreads(); }                    \
    }

#define STAGE_A(SRC, ROWSEL)                                                   \
    {                                                                          \
        int s = tid & 31;                                                      \
        int li = base + s;                                                     \
        int rsel = -1;                                                         \
        if (li < cnt) { int nn = ROWSEL; rsel = nn; }                          \
        _Pragma("unroll")                                                      \
        for (int pass = 0; pass < 16; pass++) {                                \
            int kq = (tid >> 5) + 4 * pass;                                    \
            float4 v = make_float4(0.f, 0.f, 0.f, 0.f);                        \
            if (rsel >= 0) v = __ldg((const float4*)(SRC + rsel * 256 + kq * 4)); \
            Ast[(kq * 4 + 0) * 32 + s] = v.x;                                  \
            Ast[(kq * 4 + 1) * 32 + s] = v.y;                                  \
            Ast[(kq * 4 + 2) * 32 + s] = v.z;                                  \
            Ast[(kq * 4 + 3) * 32 + s] = v.w;                                  \
        }                                                                      \
    }

// Level-3 GEMM (blocks 0-271) + suffix-table construction (blocks 272-303;
// g_S is only read by k_gemm4, so it can be built concurrently with gemm3).
__global__ void __launch_bounds__(128) k_gemm3(
    const float* __restrict__ B,  const float* __restrict__ c5,
    const float* __restrict__ c6, const float* __restrict__ c7)
{
    __shared__ float Ast[256 * 32];
    __shared__ float Bs[2 * 32 * 128];
    int tid = threadIdx.x;
    int bx = blockIdx.x;

    if (bx >= 272) {
        // ---- suffix: S[(a,bc)][row] = core5[row,a,:64] @ U[bc] ----
        if (tid == 0) {   // ticket arrival (does not read g_cnt3)
            int old = atomicAdd(&g_done3, 1);
            if (old == GRID3 - 1) {
#pragma unroll
                for (int j = 0; j < 8; j++) g_cnt3[j] = 0;
                g_done3 = 0;
            }
        }
        __shared__ float sc7[64];
        float* sA = Ast;          // 4352 floats used
        float* sB = Bs;           // 4352 floats used
        int b2 = bx - 272;
        int adig = b2 >> 2, row0 = (b2 & 3) * 64;
        if (tid < 64) sc7[tid] = c7[tid];
        for (int e = tid; e < 4096; e += 128) sA[e] = c6[e];   // stage c6
        __syncthreads();
        // U[bc][j] from smem
        for (int e = tid; e < 4096; e += 128) {
            int j = e >> 6, bc = e & 63;
            int b = bc >> 3, cd = bc & 7;
            float acc = 0.f;
#pragma unroll
            for (int i = 0; i < 8; i++)
                acc += sA[(j * 8 + b) * 8 + i] * sc7[i * 8 + cd];
            sB[j * 68 + bc] = acc;
        }
        __syncthreads();
        // stage c5 rows transposed (coalesced loads)
        for (int e = tid; e < 4096; e += 128) {
            int r = e >> 6, j = e & 63;
            sA[j * 68 + r] = c5[((row0 + r) * 8 + adig) * 64 + j];
        }
        __syncthreads();
        // 128 threads: rt = tid&15 (4 rows), bct = tid>>4 (8 bc values)
        int rt = tid & 15, bct = tid >> 4;
        float acc[8][4] = {};
        for (int j = 0; j < 64; j++) {
            float4 av = *(const float4*)&sA[j * 68 + rt * 4];
#pragma unroll
            for (int jj = 0; jj < 8; jj++) {
                float uv = sB[j * 68 + bct * 8 + jj];
                acc[jj][0] += av.x * uv; acc[jj][1] += av.y * uv;
                acc[jj][2] += av.z * uv; acc[jj][3] += av.w * uv;
            }
        }
#pragma unroll
        for (int jj = 0; jj < 8; jj++) {
            int q = adig * 64 + bct * 8 + jj;
            *(float4*)&g_S[q * 256 + row0 + rt * 4] =
                make_float4(acc[jj][0], acc[jj][1], acc[jj][2], acc[jj][3]);
        }
        return;
    }

    int t = bx >> 1, half = bx & 1;
    int2 cb = tile_map(g_cnt3, t);
    int c = cb.x, base = cb.y;
    int cnt = (c >= 0) ? g_cnt3[c] : 0;
    TICKET_CLEAN(g_done3, g_cnt3, GRID3);
    if (c < 0) return;

    STAGE_A(g_P, g_p[g_b3[c * NS + li]]);
    __syncthreads();

    int colg = tid & 31, sg = tid >> 5;
    int brow = tid >> 5, bcol = (tid & 31) * 4;
    const float* Bg = B + c * 256 + half * 128;
    float4 nb[8];
    u64 acc[4][4] = {};
    GEMM_MAIN();

#pragma unroll
    for (int p = 0; p < 4; p++) {
        float lo0, lo1, lo2, lo3, hi0, hi1, hi2, hi3;
        UNPACK64(lo0, hi0, acc[p][0]); UNPACK64(lo1, hi1, acc[p][1]);
        UNPACK64(lo2, hi2, acc[p][2]); UNPACK64(lo3, hi3, acc[p][3]);
        int l0 = base + sg * 8 + 2 * p, l1 = l0 + 1;
        int n0 = (l0 < cnt) ? g_b3[c * NS + l0] : -1;
        int n1 = (l1 < cnt) ? g_b3[c * NS + l1] : -1;
        if (n0 >= 0) *(float4*)&g_V1[n0 * 256 + half * 128 + colg * 4] =
            make_float4(lo0, lo1, lo2, lo3);
        if (n1 >= 0) *(float4*)&g_V1[n1 * 256 + half * 128 + colg * 4] =
            make_float4(hi0, hi1, hi2, hi3);
    }
}

// Level-4 + suffix dot: out[n] += (V1[n]@C4[c])[half] . S[q[n]][half]
__global__ void __launch_bounds__(128) k_gemm4(const float* __restrict__ B,
                                               float* __restrict__ out) {
    __shared__ float Ast[256 * 32];
    __shared__ float Bs[2 * 32 * 128];
    int tid = threadIdx.x;
    int t = blockIdx.x >> 1, half = blockIdx.x & 1;
    int2 cb = tile_map(g_cnt4, t);
    int c = cb.x, base = cb.y;
    int cnt = (c >= 0) ? g_cnt4[c] : 0;
    TICKET_CLEAN(g_done4, g_cnt4, GRID4);
    if (c < 0) return;

    STAGE_A(g_V1, g_b4[c * NS + li]);
    __syncthreads();

    int colg = tid & 31, sg = tid >> 5;
    int brow = tid >> 5, bcol = (tid & 31) * 4;
    const float* Bg = B + c * 256 + half * 128;
    float4 nb[8];
    u64 acc[4][4] = {};
    GEMM_MAIN();

    float part[8];
#pragma unroll
    for (int p = 0; p < 4; p++) {
        float lo0, lo1, lo2, lo3, hi0, hi1, hi2, hi3;
        UNPACK64(lo0, hi0, acc[p][0]); UNPACK64(lo1, hi1, acc[p][1]);
        UNPACK64(lo2, hi2, acc[p][2]); UNPACK64(lo3, hi3, acc[p][3]);
        int l0 = base + sg * 8 + 2 * p, l1 = l0 + 1;
        int nn0 = (l0 < cnt) ? g_b4[c * NS + l0] : -1;
        int nn1 = (l1 < cnt) ? g_b4[c * NS + l1] : -1;
        int q0 = (nn0 >= 0) ? g_q[nn0] : 0;
        int q1 = (nn1 >= 0) ? g_q[nn1] : 0;
        float4 s0 = *(const float4*)(g_S + q0 * 256 + half * 128 + colg * 4);
        float4 s1 = *(const float4*)(g_S + q1 * 256 + half * 128 + colg * 4);
        part[2 * p]     = lo0 * s0.x + lo1 * s0.y + lo2 * s0.z + lo3 * s0.w;
        part[2 * p + 1] = hi0 * s1.x + hi1 * s1.y + hi2 * s1.z + hi3 * s1.w;
    }
#pragma unroll
    for (int i = 0; i < 8; i++) {
#pragma unroll
        for (int off = 16; off > 0; off >>= 1)
            part[i] += __shfl_xor_sync(0xffffffffu, part[i], off);
    }
    if (colg == 0) {
        // two halves accumulate into out[n]; a+b == b+a bitwise -> deterministic
#pragma unroll
        for (int i = 0; i < 8; i++) {
            int l = base + sg * 8 + i;
            if (l < cnt) atomicAdd(out + g_b4[c * NS + l], part[i]);
        }
    }
}

// ---------------------------------------------------------------------------
extern "C" void kernel_launch(void* const* d_in, const int* in_sizes, int n_in,
                              void* d_out, int out_size) {
    const float* core0 = (const float*)d_in[0];
    const float* core1 = (const float*)d_in[1];
    const float* core2 = (const float*)d_in[2];
    const float* core3 = (const float*)d_in[3];
    const float* core4 = (const float*)d_in[4];
    const float* core5 = (const float*)d_in[5];
    const float* core6 = (const float*)d_in[6];
    const float* core7 = (const float*)d_in[7];
    const int*   coords = (const int*)d_in[8];
    float* out = (float*)d_out;

    k_setup<<<48, 256>>>(core0, core1, core2, coords, out);
    k_gemm3<<<GRID3, 128>>>(core3, core5, core6, core7);
    k_gemm4<<<GRID4, 128>>>(core4, out);
}